// round 9
// baseline (speedup 1.0000x reference)
#include <cuda_runtime.h>
#include <cstdint>
#include <math.h>

// Problem constants
constexpr int BB = 1024;
constexpr int TT = 120;
constexpr int EE = 50;
constexpr int HH = 300;
constexpr int CC = 5;
constexpr int KTOT = EE + HH;        // 350
constexpr int KPAD = 352;            // 22 * 16
constexpr int NZ = 4 * HH;           // 1200
constexpr int NZP = 1224;            // 17 * 72 padded (permuted) cols

// GEMM tiling
constexpr int GM = 128;              // rows per block
constexpr int GN = 72;               // cols per block = 18 positions * 4 gates
constexpr int KC = 16;               // K chunk (cp.async double buffered)
constexpr int NCHUNK = KPAD / KC;    // 22
constexpr int POSB = 18;             // positions per block
constexpr int NTHR = 512;            // threads per block (16 warps)

// CE kernel
constexpr int TOKENS = BB * TT;                   // 122880
constexpr int CE_TB = 128;
constexpr int CE_BLOCKS = TOKENS / CE_TB;         // 960

// ----------------- device scratch (no cudaMalloc allowed) -----------------
__device__ float  g_xT[TT * EE * BB];        // x transposed [t][e][b]   24.6 MB
__device__ float2 g_Wdup[KPAD * NZP];        // permuted+dup W            3.45 MB
__device__ float  g_biasP[NZP];              // permuted bias
__device__ float  g_hT[2][HH * BB];          // h transposed [h][b], x2
__device__ float  g_c[HH * BB];              // cell state   [p][b]
__device__ float  g_hs[TT * HH * BB];        // hidden states [t][h][b]   147 MB
__device__ double g_bsum[CE_BLOCKS];
__device__ int    g_bcnt[CE_BLOCKS];
__device__ int    g_mask_is_byte;

// ----------------- helpers -----------------
__device__ __forceinline__ void fma2(unsigned long long& d,
                                     unsigned long long a,
                                     unsigned long long b) {
    asm("fma.rn.f32x2 %0, %1, %2, %0;" : "+l"(d) : "l"(a), "l"(b));
}

__device__ __forceinline__ float rcp_fast(float x) {
    float y;
    asm("rcp.approx.f32 %0, %1;" : "=f"(y) : "f"(x));
    return y;
}

// exp(x) with zero MUFU: FMA-only range reduction + 2^f poly + exponent add.
__device__ __forceinline__ float exp_fma(float x) {
    float x2 = x * 1.4426950408889634f;
    x2 = fminf(fmaxf(x2, -30.0f), 30.0f);
    float biased = x2 + 12582912.0f;            // 1.5 * 2^23
    int   ni = __float_as_int(biased) - 0x4B400000;
    float n = biased - 12582912.0f;
    float f = x2 - n;
    float p = 1.5403530e-4f;
    p = fmaf(p, f, 1.3333558e-3f);
    p = fmaf(p, f, 9.6181291e-3f);
    p = fmaf(p, f, 5.5504109e-2f);
    p = fmaf(p, f, 2.4022651e-1f);
    p = fmaf(p, f, 6.9314718e-1f);
    p = fmaf(p, f, 1.0f);
    return __int_as_float(__float_as_int(p) + (ni << 23));
}

// LSTM pointwise update (validated: FMA-exp + 2 RCP).
__device__ __forceinline__ void lstm_point(float iv, float jv, float fv, float ov,
                                           float c, float& cn, float& hn) {
    float ef = exp_fma(-(fv + 1.0f));
    float ei = exp_fma(-iv);
    float ej = exp_fma(2.0f * jv);
    float eo = exp_fma(-ov);
    float Af = 1.0f + ef;
    float Ai = 1.0f + ei;
    float Aj = ej + 1.0f;
    float Nj = ej - 1.0f;
    float AiAj = Ai * Aj;
    float num = fmaf(c, AiAj, Nj * Af);
    cn = num * rcp_fast(Af * AiAj);
    float ec = exp_fma(2.0f * cn);
    hn = (ec - 1.0f) * rcp_fast((1.0f + eo) * (ec + 1.0f));
}

__device__ __forceinline__ void cp16(uint32_t dst_smem, const void* src, int srcsize) {
    asm volatile("cp.async.cg.shared.global [%0], [%1], 16, %2;"
                 :: "r"(dst_smem), "l"(src), "r"(srcsize));
}
__device__ __forceinline__ void cp_commit() {
    asm volatile("cp.async.commit_group;");
}
template <int N>
__device__ __forceinline__ void cp_wait() {
    asm volatile("cp.async.wait_group %0;" :: "n"(N));
}

// ----------------- setup kernels -----------------

__global__ void initdetect_k(const unsigned int* __restrict__ mw) {
    int idx = blockIdx.x * blockDim.x + threadIdx.x;
    if (idx < HH * BB) {
        g_hT[0][idx] = 0.f;
        g_hT[1][idx] = 0.f;
        g_c[idx] = 0.f;
    }
    if (idx < TOKENS / 4) {
        if (mw[idx] > 1u) g_mask_is_byte = 1;   // benign race, same value
    }
}

// Permuted + padded + duplicated weights: permuted col c' = 4p+g,
// original col = g*300 + p. g_Wdup[k*NZP + c'] = (w, w). Also permuted bias.
__global__ void wpad_k(const float* __restrict__ Wx,
                       const float* __restrict__ Wh,
                       const float* __restrict__ bias) {
    int idx = blockIdx.x * blockDim.x + threadIdx.x;
    if (idx < KPAD * NZP) {
        int k = idx / NZP, cp = idx % NZP;
        float v = 0.f;
        if (cp < NZ) {
            int p = cp >> 2, g = cp & 3;
            int co = g * HH + p;
            if (k < EE)        v = Wx[k * NZ + co];
            else if (k < KTOT) v = Wh[(k - EE) * NZ + co];
        }
        g_Wdup[idx] = make_float2(v, v);
    }
    if (idx < NZP) {
        float v = 0.f;
        if (idx < NZ) v = bias[(idx & 3) * HH + (idx >> 2)];
        g_biasP[idx] = v;
    }
}

// Gather embeddings transposed via smem transpose.
__global__ void gather_k(const int* __restrict__ tokens,
                         const float* __restrict__ emb) {
    __shared__ int   toks[64];
    __shared__ float tile[EE][65];
    const int t = blockIdx.x;
    const int b0 = blockIdx.y * 64;
    const int tid = threadIdx.x;
    const int warp = tid >> 5, lane = tid & 31;

    if (tid < 64) toks[tid] = tokens[(b0 + tid) * TT + t];
    __syncthreads();
    for (int row = warp; row < 64; row += 8) {
        const float* er = emb + (size_t)toks[row] * EE;
        for (int e = lane; e < EE; e += 32) tile[e][row] = er[e];
    }
    __syncthreads();
    for (int e = warp; e < EE; e += 8) {
        float* dst = g_xT + ((size_t)t * EE + e) * BB + b0;
        dst[lane]      = tile[e][lane];
        dst[lane + 32] = tile[e][lane + 32];
    }
}

// --------- fused per-step kernel: GEMM + gates + state update --------------
// grid (8, 17), 512 threads (16 warps/SM). GEMM thread (tx=tid&7, ty=tid>>3):
//   rows r0 + 2*ty, 2*ty+1 (one f32x2 pair), cols: pairs (2tx+16jg, +1)
//   jg=0..3, plus single col 64+tx. cp.async double-buffered KC=16.
// Epilogue: z-tile staged via smem (reusing stage buffers), full LSTM update.
constexpr int ZS_LD = 130;                                 // padded row stride
constexpr int SRAW_BYTES = GN * ZS_LD * 4;                 // 37440 >= 34816
__global__ __launch_bounds__(NTHR) void lstm_step_k(int t) {
    __shared__ __align__(16) char s_raw[SRAW_BYTES];
    __shared__ float bias_s[GN];

    float* const Asb = reinterpret_cast<float*>(s_raw);            // [2][16][128]
    float* const Wsb = reinterpret_cast<float*>(s_raw + 16384);    // [2][16][72][2]
    float* const zs  = reinterpret_cast<float*>(s_raw);            // [72][130]

    const int tid = threadIdx.x;
    const int tx = tid & 7;
    const int ty = tid >> 3;                 // 0..63
    const int r0 = blockIdx.x * GM;
    const int c0 = blockIdx.y * GN;
    const int pbase = blockIdx.y * POSB;
    const float* __restrict__ hT = g_hT[t & 1];
    const float* __restrict__ xTt = g_xT + (size_t)t * EE * BB;

    const uint32_t sAs = (uint32_t)__cvta_generic_to_shared(Asb);
    const uint32_t sWs = (uint32_t)__cvta_generic_to_shared(Wsb);

    if (tid < GN) bias_s[tid] = g_biasP[c0 + tid];

    unsigned long long acc[9];
#pragma unroll
    for (int j = 0; j < 9; ++j) acc[j] = 0ull;

    auto load_stage = [&](int s, int k0) {
        // A tile: 16x128 floats = 512 x 16B ops (1/thread)
        {
            int kc = tid >> 5;                 // 0..15
            int seg = tid & 31;                // 16B segment in 128-float row
            int k = k0 + kc;
            const float* src;
            int sz = 16;
            if (k < EE)        src = xTt + (size_t)k * BB + r0 + seg * 4;
            else if (k < KTOT) src = hT + (size_t)(k - EE) * BB + r0 + seg * 4;
            else             { src = hT; sz = 0; }
            cp16(sAs + (uint32_t)(s * (KC * GM) + kc * GM + seg * 4) * 4, src, sz);
        }
        // W tile: 16x72 float2 = 576 x 16B ops (tid<64 do a second one)
        const float2* wbase = g_Wdup + (size_t)k0 * NZP + c0;
#pragma unroll
        for (int n = 0; n < 2; ++n) {
            int idx = tid + (n << 9);
            if (idx < KC * 36) {               // 36 x 16B per kc row
                int kc = idx / 36;
                int off = idx - kc * 36;
                const void* src = (const void*)(wbase + (size_t)kc * NZP + off * 2);
                cp16(sWs + (uint32_t)(s * (KC * GN * 2) + kc * (GN * 2)) * 4
                         + (uint32_t)off * 16, src, 16);
            }
        }
    };

    load_stage(0, 0);
    cp_commit();

    const int ty2 = ty * 2;
    for (int chunk = 0; chunk < NCHUNK; ++chunk) {
        const int cur = chunk & 1;
        if (chunk + 1 < NCHUNK) {
            load_stage(cur ^ 1, (chunk + 1) * KC);
            cp_commit();
            cp_wait<1>();          // stage `cur` resident
        } else {
            cp_wait<0>();
        }
        __syncthreads();

        const float* Ab = Asb + cur * (KC * GM);
        const float* Wb = Wsb + cur * (KC * GN * 2);
#pragma unroll
        for (int kc = 0; kc < KC; ++kc) {
            unsigned long long a0 =
                *reinterpret_cast<const unsigned long long*>(&Ab[kc * GM + ty2]);
            const float* wrow = Wb + kc * (GN * 2);
#pragma unroll
            for (int jg = 0; jg < 4; ++jg) {
                ulonglong2 wv = *reinterpret_cast<const ulonglong2*>(
                    &wrow[(2 * tx + 16 * jg) * 2]);
                fma2(acc[2 * jg],     a0, wv.x);
                fma2(acc[2 * jg + 1], a0, wv.y);
            }
            unsigned long long w8 = *reinterpret_cast<const unsigned long long*>(
                &wrow[(64 + tx) * 2]);
            fma2(acc[8], a0, w8);
        }
        __syncthreads();   // stage `cur` fully consumed before refill/reuse
    }

    // ---- stage z-tile into smem (overlaps the now-dead stage buffers) ----
#pragma unroll
    for (int j = 0; j < 9; ++j) {
        int col = (j < 8) ? (2 * tx + 16 * (j >> 1) + (j & 1)) : (64 + tx);
        *reinterpret_cast<unsigned long long*>(&zs[col * ZS_LD + ty2]) = acc[j];
    }
    __syncthreads();

    // ---- gate math: thread -> (r = tid&127, half = tid>>7 in 0..3) ----
    const int r = tid & 127;
    const int half = tid >> 7;
    const int b = r0 + r;
#pragma unroll
    for (int pp = 0; pp < 5; ++pp) {
        int pl = pp * 4 + half;
        int pg = pbase + pl;
        if (pl < POSB && pg < HH) {
            float iv = zs[(4 * pl + 0) * ZS_LD + r] + bias_s[4 * pl + 0];
            float jv = zs[(4 * pl + 1) * ZS_LD + r] + bias_s[4 * pl + 1];
            float fv = zs[(4 * pl + 2) * ZS_LD + r] + bias_s[4 * pl + 2];
            float ov = zs[(4 * pl + 3) * ZS_LD + r] + bias_s[4 * pl + 3];
            int sidx = pg * BB + b;
            float c = g_c[sidx];
            float cn, hn;
            lstm_point(iv, jv, fv, ov, c, cn, hn);
            g_c[sidx] = cn;
            g_hs[((size_t)t * HH + pg) * BB + b] = hn;
            g_hT[(t + 1) & 1][sidx] = hn;
        }
    }
}

// ----------------- CE: projection + log-softmax + masked sum ----------------
__global__ void ce_k(const float* __restrict__ U, const float* __restrict__ b2,
                     const int* __restrict__ labels,
                     const void* __restrict__ maskp)
{
    __shared__ float Us[HH * CC];
    __shared__ float b2s[CC];
    __shared__ double sd[CE_TB];
    __shared__ int    sc[CE_TB];

    const int tid = threadIdx.x;
    const int t = blockIdx.x >> 3;
    const int b = ((blockIdx.x & 7) << 7) + tid;

    for (int i = tid; i < HH * CC; i += CE_TB) Us[i] = U[i];
    if (tid < CC) b2s[tid] = b2[tid];
    __syncthreads();

    float s0 = b2s[0], s1 = b2s[1], s2 = b2s[2], s3 = b2s[3], s4 = b2s[4];
    const float* hp = g_hs + (size_t)t * HH * BB + b;
#pragma unroll 4
    for (int k = 0; k < HH; ++k) {
        float hv = hp[(size_t)k * BB];
        const float* ur = &Us[k * CC];
        s0 += hv * ur[0]; s1 += hv * ur[1]; s2 += hv * ur[2];
        s3 += hv * ur[3]; s4 += hv * ur[4];
    }

    float m = fmaxf(fmaxf(fmaxf(s0, s1), fmaxf(s2, s3)), s4);
    float sum = __expf(s0 - m) + __expf(s1 - m) + __expf(s2 - m)
              + __expf(s3 - m) + __expf(s4 - m);
    float lse = m + __logf(sum);
    int lab = labels[b * TT + t];
    float lc = (lab == 0) ? s0 : (lab == 1) ? s1 : (lab == 2) ? s2
             : (lab == 3) ? s3 : s4;
    float ce = lse - lc;
    int mk;
    if (g_mask_is_byte) mk = (((const unsigned char*)maskp)[b * TT + t] != 0);
    else                mk = (((const int*)maskp)[b * TT + t] != 0);

    sd[tid] = mk ? (double)ce : 0.0;
    sc[tid] = mk;
    __syncthreads();
    for (int off = CE_TB / 2; off; off >>= 1) {
        if (tid < off) { sd[tid] += sd[tid + off]; sc[tid] += sc[tid + off]; }
        __syncthreads();
    }
    if (tid == 0) { g_bsum[blockIdx.x] = sd[0]; g_bcnt[blockIdx.x] = sc[0]; }
}

__global__ void fin_k(float* out) {
    __shared__ double sd[256];
    __shared__ int    sc[256];
    int i = threadIdx.x;
    double s = 0.0; int c = 0;
    for (int j = i; j < CE_BLOCKS; j += 256) { s += g_bsum[j]; c += g_bcnt[j]; }
    sd[i] = s; sc[i] = c;
    __syncthreads();
    for (int off = 128; off; off >>= 1) {
        if (i < off) { sd[i] += sd[i + off]; sc[i] += sc[i + off]; }
        __syncthreads();
    }
    if (i == 0) out[0] = (float)(sd[0] / (double)sc[0]);
}

// ----------------- launcher -----------------
extern "C" void kernel_launch(void* const* d_in, const int* in_sizes, int n_in,
                              void* d_out, int out_size)
{
    const int*   tokens = (const int*)d_in[0];
    const int*   labels = (const int*)d_in[1];
    const void*  mask   = d_in[2];
    const float* emb    = (const float*)d_in[3];
    const float* Wx     = (const float*)d_in[4];
    const float* Wh     = (const float*)d_in[5];
    const float* bias   = (const float*)d_in[6];
    const float* U      = (const float*)d_in[7];
    const float* b2     = (const float*)d_in[8];
    float* out = (float*)d_out;

    initdetect_k<<<(HH * BB + 255) / 256, 256>>>((const unsigned int*)mask);
    wpad_k<<<(KPAD * NZP + 255) / 256, 256>>>(Wx, Wh, bias);
    gather_k<<<dim3(TT, BB / 64), 256>>>(tokens, emb);

    dim3 ggrid(BB / GM, NZP / GN);                 // (8, 17) = 136 blocks
    for (int t = 0; t < TT; ++t) {
        lstm_step_k<<<ggrid, NTHR>>>(t);           // t=0 is launch #3 (profiled)
    }

    ce_k<<<CE_BLOCKS, CE_TB>>>(U, b2, labels, mask);
    fin_k<<<1, 256>>>(out);
    (void)in_sizes; (void)n_in; (void)out_size;
}

// round 11
// speedup vs baseline: 6.2915x; 6.2915x over previous
#include <cuda_runtime.h>
#include <cuda_bf16.h>
#include <cstdint>
#include <math.h>

// Problem constants
constexpr int BB = 1024;
constexpr int TT = 120;
constexpr int EE = 50;
constexpr int HH = 300;
constexpr int CC = 5;
constexpr int KTOT = EE + HH;        // 350
constexpr int KP = 352;              // K padded (22 * 16), cols 350/351 zero
constexpr int NZ = 4 * HH;           // 1200
constexpr int NZP = 1224;            // 17 * 72 permuted cols

// Tiling: grid (8, 17), 256 threads (8 warps). Warp = one 16-row M-tile.
constexpr int GM = 128;
constexpr int GN = 72;               // 18 positions * 4 gates
constexpr int POSB = 18;
constexpr int KT = KP / 16;          // 22 k-tiles
constexpr int NT = GN / 8;           // 9 n-tiles

// smem: A[128][360] bf16 + W[72][360] bf16 (720B row stride, conflict-free)
constexpr int AS_STRIDE = 720;       // bytes per row
constexpr int AS_BYTES = GM * AS_STRIDE;       // 92160
constexpr int WS_BYTES = GN * AS_STRIDE;       // 51840
constexpr int DYN_BYTES = AS_BYTES + WS_BYTES; // 144000
constexpr int HALF_ELE = 176;        // K elements per load half
constexpr int HALF_B = HALF_ELE * 2; // 352 bytes
constexpr int ACH_H = GM * 22;       // A chunks per half (22 x 16B per row)
constexpr int WCH_H = GN * 22;

// CE kernel
constexpr int TOKENS = BB * TT;
constexpr int CE_TB = 128;
constexpr int CE_BLOCKS = TOKENS / CE_TB;      // 960

// ----------------- device scratch (no cudaMalloc allowed) -----------------
__device__ __align__(16) __nv_bfloat16 g_A[(TT + 1) * BB * KP]; // 87.2 MB
__device__ __align__(16) __nv_bfloat16 g_W[NZP * KP];           // 0.86 MB
__device__ float  g_biasP[NZP];
__device__ float  g_c[HH * BB];                 // cell state [p][b]
__device__ float  g_hs[TT * HH * BB];           // hidden [t][p][b]  147 MB
__device__ double g_bsum[CE_BLOCKS];
__device__ int    g_bcnt[CE_BLOCKS];
__device__ int    g_mask_is_byte;

// ----------------- scalar helpers -----------------
__device__ __forceinline__ float rcp_fast(float x) {
    float y;
    asm("rcp.approx.f32 %0, %1;" : "=f"(y) : "f"(x));
    return y;
}

// exp(x) with zero MUFU: FMA-only range reduction + 2^f poly + exponent add.
__device__ __forceinline__ float exp_fma(float x) {
    float x2 = x * 1.4426950408889634f;
    x2 = fminf(fmaxf(x2, -30.0f), 30.0f);
    float biased = x2 + 12582912.0f;            // 1.5 * 2^23
    int   ni = __float_as_int(biased) - 0x4B400000;
    float n = biased - 12582912.0f;
    float f = x2 - n;
    float p = 1.5403530e-4f;
    p = fmaf(p, f, 1.3333558e-3f);
    p = fmaf(p, f, 9.6181291e-3f);
    p = fmaf(p, f, 5.5504109e-2f);
    p = fmaf(p, f, 2.4022651e-1f);
    p = fmaf(p, f, 6.9314718e-1f);
    p = fmaf(p, f, 1.0f);
    return __int_as_float(__float_as_int(p) + (ni << 23));
}

// LSTM pointwise update (validated: FMA-exp + 2 RCP).
__device__ __forceinline__ void lstm_point(float iv, float jv, float fv, float ov,
                                           float c, float& cn, float& hn) {
    float ef = exp_fma(-(fv + 1.0f));
    float ei = exp_fma(-iv);
    float ej = exp_fma(2.0f * jv);
    float eo = exp_fma(-ov);
    float Af = 1.0f + ef;
    float Ai = 1.0f + ei;
    float Aj = ej + 1.0f;
    float Nj = ej - 1.0f;
    float AiAj = Ai * Aj;
    float num = fmaf(c, AiAj, Nj * Af);
    cn = num * rcp_fast(Af * AiAj);
    float ec = exp_fma(2.0f * cn);
    hn = (ec - 1.0f) * rcp_fast((1.0f + eo) * (ec + 1.0f));
}

// ----------------- async copy helpers -----------------
__device__ __forceinline__ void cp16(uint32_t dst_smem, const void* src) {
    asm volatile("cp.async.cg.shared.global [%0], [%1], 16;"
                 :: "r"(dst_smem), "l"(src));
}
__device__ __forceinline__ void cp_commit() {
    asm volatile("cp.async.commit_group;");
}
template <int N>
__device__ __forceinline__ void cp_wait() {
    asm volatile("cp.async.wait_group %0;" :: "n"(N));
}

// mma.sync m16n8k16 bf16 (sm_80+, works on sm_100 fallback HMMA path)
__device__ __forceinline__ void mma16816(float& d0, float& d1, float& d2, float& d3,
                                         uint32_t a0, uint32_t a1, uint32_t a2,
                                         uint32_t a3, uint32_t b0, uint32_t b1) {
    asm volatile(
        "mma.sync.aligned.m16n8k16.row.col.f32.bf16.bf16.f32 "
        "{%0,%1,%2,%3}, {%4,%5,%6,%7}, {%8,%9}, {%0,%1,%2,%3};"
        : "+f"(d0), "+f"(d1), "+f"(d2), "+f"(d3)
        : "r"(a0), "r"(a1), "r"(a2), "r"(a3), "r"(b0), "r"(b1));
}

// ----------------- setup kernels -----------------

// Zero whole A image (k-pad cols, t=0 h region; deterministic per replay).
__global__ void zeroA_k() {
    size_t n = (size_t)(TT + 1) * BB * KP * 2 / 16;
    uint4 z = make_uint4(0, 0, 0, 0);
    for (size_t i = (size_t)blockIdx.x * blockDim.x + threadIdx.x;
         i < n; i += (size_t)gridDim.x * blockDim.x)
        reinterpret_cast<uint4*>(g_A)[i] = z;
}

__global__ void initdetect_k(const unsigned int* __restrict__ mw) {
    int idx = blockIdx.x * blockDim.x + threadIdx.x;
    if (idx < HH * BB) g_c[idx] = 0.f;
    if (idx < TOKENS / 4) {
        if (mw[idx] > 1u) g_mask_is_byte = 1;   // benign race, same value
    }
}

// Permuted bf16 weights g_W[c'][k], c' = 4p+g (orig col g*300+p); bias too.
__global__ void wbuild_k(const float* __restrict__ Wx,
                         const float* __restrict__ Wh,
                         const float* __restrict__ bias) {
    int idx = blockIdx.x * blockDim.x + threadIdx.x;
    if (idx < NZP * KP) {
        int cp = idx / KP, k = idx % KP;
        float v = 0.f;
        if (cp < NZ && k < KTOT) {
            int p = cp >> 2, g = cp & 3;
            v = (k < EE) ? Wx[k * NZ + g * HH + p] : Wh[(k - EE) * NZ + g * HH + p];
        }
        g_W[idx] = __float2bfloat16(v);
    }
    if (idx < NZP) {
        float v = 0.f;
        if (idx < NZ) v = bias[(idx & 3) * HH + (idx >> 2)];
        g_biasP[idx] = v;
    }
}

// Gather embeddings as bf16 pairs into A images, k = 0..49.
__global__ void gather_k(const int* __restrict__ tokens,
                         const float* __restrict__ emb) {
    int idx = blockIdx.x * blockDim.x + threadIdx.x;
    if (idx >= TOKENS) return;
    int b = idx / TT, t = idx - b * TT;
    const float* er = emb + (size_t)tokens[idx] * EE;
    uint32_t* dst = reinterpret_cast<uint32_t*>(
        g_A + ((size_t)t * BB + b) * KP);
#pragma unroll
    for (int q = 0; q < EE / 2; ++q) {
        __nv_bfloat162 p2 = __floats2bfloat162_rn(er[2 * q], er[2 * q + 1]);
        dst[q] = *reinterpret_cast<uint32_t*>(&p2);
    }
}

// --------- fused per-step kernel: bf16 mma.sync GEMM + gates + update ------
// grid (8, 17), 256 threads (8 warps). Warp w: M-tile rows w*16..+15, all
// 72 cols, 22 K-tiles of m16n8k16. Fragment loads are direct 4B LDS from
// layouts matching the PTX fragment maps (no ldmatrix needed).
__global__ __launch_bounds__(256) void lstm_step_k(int t) {
    extern __shared__ __align__(16) char dyn[];
    __shared__ float bias_s[GN];

    char* const As = dyn;                       // [128][720B]
    char* const Ws = dyn + AS_BYTES;            // [72][720B]
    const uint32_t sA = (uint32_t)__cvta_generic_to_shared(As);
    const uint32_t sW = (uint32_t)__cvta_generic_to_shared(Ws);

    const int tid = threadIdx.x;
    const int warp = tid >> 5;
    const int lane = tid & 31;
    const int g = lane >> 2;         // groupID
    const int tig = lane & 3;        // thread-in-group
    const int rb = blockIdx.x;
    const int cbk = blockIdx.y;
    const int pblk = cbk * POSB;

    const char* gAb = reinterpret_cast<const char*>(
        g_A + ((size_t)t * BB + rb * GM) * KP);
    const char* gWb = reinterpret_cast<const char*>(g_W + (size_t)cbk * GN * KP);

    // two K-halves, each 22 x 16B chunks per row
    auto load_half = [&](int h) {
        const int hb = h * HALF_B;
        for (int i = tid; i < ACH_H; i += 256) {
            int r = i / 22, c = i - r * 22;
            cp16(sA + r * AS_STRIDE + hb + c * 16, gAb + r * (KP * 2) + hb + c * 16);
        }
        for (int i = tid; i < WCH_H; i += 256) {
            int r = i / 22, c = i - r * 22;
            cp16(sW + r * AS_STRIDE + hb + c * 16, gWb + r * (KP * 2) + hb + c * 16);
        }
    };
    load_half(0);
    cp_commit();
    load_half(1);
    cp_commit();
    if (tid < GN) bias_s[tid] = g_biasP[cbk * GN + tid];

    float acc[NT][4];
#pragma unroll
    for (int j = 0; j < NT; ++j)
#pragma unroll
        for (int e = 0; e < 4; ++e) acc[j][e] = 0.f;

    const int m0 = warp * 16;
    const char* aRow0 = As + (m0 + g) * AS_STRIDE + tig * 4;
    const char* aRow1 = As + (m0 + g + 8) * AS_STRIDE + tig * 4;
    const char* wCol = Ws + g * AS_STRIDE + tig * 4;

    cp_wait<1>();
    __syncthreads();

#pragma unroll
    for (int half = 0; half < 2; ++half) {
        if (half == 1) {
            cp_wait<0>();
            __syncthreads();
        }
#pragma unroll
        for (int kk = 0; kk < 11; ++kk) {
            const int koff = (half * 11 + kk) * 32;      // k0*2 bytes
            uint32_t a0 = *reinterpret_cast<const uint32_t*>(aRow0 + koff);
            uint32_t a1 = *reinterpret_cast<const uint32_t*>(aRow1 + koff);
            uint32_t a2 = *reinterpret_cast<const uint32_t*>(aRow0 + koff + 16);
            uint32_t a3 = *reinterpret_cast<const uint32_t*>(aRow1 + koff + 16);
#pragma unroll
            for (int j = 0; j < NT; ++j) {
                uint32_t b0 = *reinterpret_cast<const uint32_t*>(
                    wCol + j * 8 * AS_STRIDE + koff);
                uint32_t b1 = *reinterpret_cast<const uint32_t*>(
                    wCol + j * 8 * AS_STRIDE + koff + 16);
                mma16816(acc[j][0], acc[j][1], acc[j][2], acc[j][3],
                         a0, a1, a2, a3, b0, b1);
            }
        }
    }

    // ---- epilogue (warp-local): regroup gates via shfl, LSTM update ----
    const int rowlo = rb * GM + m0 + g;
    __nv_bfloat16* gAn = g_A + ((size_t)(t + 1) * BB) * KP;

#pragma unroll
    for (int j = 0; j < NT; ++j) {
        float d0 = acc[j][0], d1 = acc[j][1], d2 = acc[j][2], d3 = acc[j][3];
        float x0 = __shfl_xor_sync(0xffffffffu, d0, 1);
        float x1 = __shfl_xor_sync(0xffffffffu, d1, 1);
        float x2 = __shfl_xor_sync(0xffffffffu, d2, 1);
        float x3 = __shfl_xor_sync(0xffffffffu, d3, 1);
        const bool odd = (tig & 1);
        float iv = odd ? x2 : d0;
        float jv = odd ? x3 : d1;
        float fv = odd ? d2 : x0;
        float ov = odd ? d3 : x1;
        int pl = 2 * j + (tig >> 1);             // local position 0..17
        int p = pblk + pl;
        int b = rowlo + (odd ? 8 : 0);
        iv += bias_s[4 * pl + 0];
        jv += bias_s[4 * pl + 1];
        fv += bias_s[4 * pl + 2];
        ov += bias_s[4 * pl + 3];
        float cn, hn = 0.f;
        if (p < HH) {
            int sidx = p * BB + b;
            float c = g_c[sidx];
            lstm_point(iv, jv, fv, ov, c, cn, hn);
            g_c[sidx] = cn;
            g_hs[((size_t)t * HH + p) * BB + b] = hn;
        }
        // pack (p even, p+1) h pair -> next step's A image (k = 50+p)
        float hp = __shfl_xor_sync(0xffffffffu, hn, 2);
        if (!(tig & 2) && p < HH) {
            __nv_bfloat162 hb = __floats2bfloat162_rn(hn, hp);
            *reinterpret_cast<uint32_t*>(&gAn[(size_t)b * KP + EE + p])
                = *reinterpret_cast<uint32_t*>(&hb);
        }
    }
}

// ----------------- CE: projection + log-softmax + masked sum ----------------
__global__ void ce_k(const float* __restrict__ U, const float* __restrict__ b2,
                     const int* __restrict__ labels,
                     const void* __restrict__ maskp)
{
    __shared__ float Us[HH * CC];
    __shared__ float b2s[CC];
    __shared__ double sd[CE_TB];
    __shared__ int    sc[CE_TB];

    const int tid = threadIdx.x;
    const int t = blockIdx.x >> 3;
    const int b = ((blockIdx.x & 7) << 7) + tid;

    for (int i = tid; i < HH * CC; i += CE_TB) Us[i] = U[i];
    if (tid < CC) b2s[tid] = b2[tid];
    __syncthreads();

    float s0 = b2s[0], s1 = b2s[1], s2 = b2s[2], s3 = b2s[3], s4 = b2s[4];
    const float* hp = g_hs + (size_t)t * HH * BB + b;
#pragma unroll 4
    for (int k = 0; k < HH; ++k) {
        float hv = hp[(size_t)k * BB];
        const float* ur = &Us[k * CC];
        s0 += hv * ur[0]; s1 += hv * ur[1]; s2 += hv * ur[2];
        s3 += hv * ur[3]; s4 += hv * ur[4];
    }

    float m = fmaxf(fmaxf(fmaxf(s0, s1), fmaxf(s2, s3)), s4);
    float sum = __expf(s0 - m) + __expf(s1 - m) + __expf(s2 - m)
              + __expf(s3 - m) + __expf(s4 - m);
    float lse = m + __logf(sum);
    int lab = labels[b * TT + t];
    float lc = (lab == 0) ? s0 : (lab == 1) ? s1 : (lab == 2) ? s2
             : (lab == 3) ? s3 : s4;
    float ce = lse - lc;
    int mk;
    if (g_mask_is_byte) mk = (((const unsigned char*)maskp)[b * TT + t] != 0);
    else                mk = (((const int*)maskp)[b * TT + t] != 0);

    sd[tid] = mk ? (double)ce : 0.0;
    sc[tid] = mk;
    __syncthreads();
    for (int off = CE_TB / 2; off; off >>= 1) {
        if (tid < off) { sd[tid] += sd[tid + off]; sc[tid] += sc[tid + off]; }
        __syncthreads();
    }
    if (tid == 0) { g_bsum[blockIdx.x] = sd[0]; g_bcnt[blockIdx.x] = sc[0]; }
}

__global__ void fin_k(float* out) {
    __shared__ double sd[256];
    __shared__ int    sc[256];
    int i = threadIdx.x;
    double s = 0.0; int c = 0;
    for (int j = i; j < CE_BLOCKS; j += 256) { s += g_bsum[j]; c += g_bcnt[j]; }
    sd[i] = s; sc[i] = c;
    __syncthreads();
    for (int off = 128; off; off >>= 1) {
        if (i < off) { sd[i] += sd[i + off]; sc[i] += sc[i + off]; }
        __syncthreads();
    }
    if (i == 0) out[0] = (float)(sd[0] / (double)sc[0]);
}

// ----------------- launcher -----------------
extern "C" void kernel_launch(void* const* d_in, const int* in_sizes, int n_in,
                              void* d_out, int out_size)
{
    const int*   tokens = (const int*)d_in[0];
    const int*   labels = (const int*)d_in[1];
    const void*  mask   = d_in[2];
    const float* emb    = (const float*)d_in[3];
    const float* Wx     = (const float*)d_in[4];
    const float* Wh     = (const float*)d_in[5];
    const float* bias   = (const float*)d_in[6];
    const float* U      = (const float*)d_in[7];
    const float* b2     = (const float*)d_in[8];
    float* out = (float*)d_out;

    static int smem_set = 0;
    if (!smem_set) {
        cudaFuncSetAttribute(lstm_step_k,
                             cudaFuncAttributeMaxDynamicSharedMemorySize,
                             DYN_BYTES);
        smem_set = 1;
    }

    zeroA_k<<<2048, 256>>>();
    initdetect_k<<<(HH * BB + 255) / 256, 256>>>((const unsigned int*)mask);
    wbuild_k<<<(NZP * KP + 255) / 256, 256>>>(Wx, Wh, bias);
    gather_k<<<(TOKENS + 255) / 256, 256>>>(tokens, emb);

    dim3 ggrid(BB / GM, NZP / GN);                 // (8, 17) = 136 blocks
    for (int t = 0; t < TT; ++t) {
        lstm_step_k<<<ggrid, 256, DYN_BYTES>>>(t);
    }

    ce_k<<<CE_BLOCKS, CE_TB>>>(U, b2, labels, mask);
    fin_k<<<1, 256>>>(out);
    (void)in_sizes; (void)n_in; (void)out_size;
}

// round 12
// speedup vs baseline: 6.3275x; 1.0057x over previous
#include <cuda_runtime.h>
#include <cuda_bf16.h>
#include <cstdint>
#include <math.h>

// Problem constants
constexpr int BB = 1024;
constexpr int TT = 120;
constexpr int EE = 50;
constexpr int HH = 300;
constexpr int CC = 5;
constexpr int KTOT = EE + HH;        // 350
constexpr int KP = 352;              // K padded (22 * 16), cols 350/351 zero
constexpr int NZ = 4 * HH;           // 1200
constexpr int NZP = 1224;            // 17 * 72 permuted cols

// Tiling: grid (8, 17), 256 threads (8 warps). Warp = one 16-row M-tile.
constexpr int GM = 128;
constexpr int GN = 72;               // 18 positions * 4 gates
constexpr int POSB = 18;
constexpr int NT = GN / 8;           // 9 n-tiles

// smem: A[128][360] bf16 + W[72][360] bf16 (720B row stride, conflict-free)
constexpr int AS_STRIDE = 720;       // bytes per row
constexpr int AS_BYTES = GM * AS_STRIDE;       // 92160
constexpr int WS_BYTES = GN * AS_STRIDE;       // 51840
constexpr int DYN_BYTES = AS_BYTES + WS_BYTES; // 144000
constexpr int HALF_B = 352;          // bytes per K-half per row
constexpr int ACH_H = GM * 22;       // A 16B chunks per half
constexpr int WCH_H = GN * 22;

// CE kernel
constexpr int TOKENS = BB * TT;
constexpr int CE_TB = 128;
constexpr int CE_BLOCKS = TOKENS / CE_TB;      // 960

// ----------------- device scratch (no cudaMalloc allowed) -----------------
// Zero-initialized at module load; every region that is ever read is either
// rewritten identically on every replay (x cols by gather, h cols of t+1 by
// step t's epilogue) or never written and must be zero (pad cols 350-351,
// t=0 h region == h0 = 0). No zero-fill kernel needed.
__device__ __align__(16) __nv_bfloat16 g_A[(TT + 1) * BB * KP]; // 87.2 MB
__device__ __align__(16) __nv_bfloat16 g_W[NZP * KP];           // 0.86 MB
__device__ float  g_biasP[NZP];
__device__ float  g_c[HH * BB];                 // cell state [p][b]
__device__ double g_bsum[CE_BLOCKS];
__device__ int    g_bcnt[CE_BLOCKS];
__device__ int    g_mask_is_byte;

// ----------------- scalar helpers -----------------
__device__ __forceinline__ float rcp_fast(float x) {
    float y;
    asm("rcp.approx.f32 %0, %1;" : "=f"(y) : "f"(x));
    return y;
}

// exp(x) with zero MUFU: FMA-only range reduction + 2^f poly + exponent add.
__device__ __forceinline__ float exp_fma(float x) {
    float x2 = x * 1.4426950408889634f;
    x2 = fminf(fmaxf(x2, -30.0f), 30.0f);
    float biased = x2 + 12582912.0f;            // 1.5 * 2^23
    int   ni = __float_as_int(biased) - 0x4B400000;
    float n = biased - 12582912.0f;
    float f = x2 - n;
    float p = 1.5403530e-4f;
    p = fmaf(p, f, 1.3333558e-3f);
    p = fmaf(p, f, 9.6181291e-3f);
    p = fmaf(p, f, 5.5504109e-2f);
    p = fmaf(p, f, 2.4022651e-1f);
    p = fmaf(p, f, 6.9314718e-1f);
    p = fmaf(p, f, 1.0f);
    return __int_as_float(__float_as_int(p) + (ni << 23));
}

// LSTM pointwise update (validated: FMA-exp + 2 RCP).
__device__ __forceinline__ void lstm_point(float iv, float jv, float fv, float ov,
                                           float c, float& cn, float& hn) {
    float ef = exp_fma(-(fv + 1.0f));
    float ei = exp_fma(-iv);
    float ej = exp_fma(2.0f * jv);
    float eo = exp_fma(-ov);
    float Af = 1.0f + ef;
    float Ai = 1.0f + ei;
    float Aj = ej + 1.0f;
    float Nj = ej - 1.0f;
    float AiAj = Ai * Aj;
    float num = fmaf(c, AiAj, Nj * Af);
    cn = num * rcp_fast(Af * AiAj);
    float ec = exp_fma(2.0f * cn);
    hn = (ec - 1.0f) * rcp_fast((1.0f + eo) * (ec + 1.0f));
}

// ----------------- async copy helpers -----------------
__device__ __forceinline__ void cp16(uint32_t dst_smem, const void* src) {
    asm volatile("cp.async.cg.shared.global [%0], [%1], 16;"
                 :: "r"(dst_smem), "l"(src));
}
__device__ __forceinline__ void cp_commit() {
    asm volatile("cp.async.commit_group;");
}
template <int N>
__device__ __forceinline__ void cp_wait() {
    asm volatile("cp.async.wait_group %0;" :: "n"(N));
}

// mma.sync m16n8k16 bf16 (sm_80+ PTX, legal on plain sm_100 target)
__device__ __forceinline__ void mma16816(float& d0, float& d1, float& d2, float& d3,
                                         uint32_t a0, uint32_t a1, uint32_t a2,
                                         uint32_t a3, uint32_t b0, uint32_t b1) {
    asm volatile(
        "mma.sync.aligned.m16n8k16.row.col.f32.bf16.bf16.f32 "
        "{%0,%1,%2,%3}, {%4,%5,%6,%7}, {%8,%9}, {%0,%1,%2,%3};"
        : "+f"(d0), "+f"(d1), "+f"(d2), "+f"(d3)
        : "r"(a0), "r"(a1), "r"(a2), "r"(a3), "r"(b0), "r"(b1));
}

// ----------------- setup kernels -----------------

__global__ void initdetect_k(const unsigned int* __restrict__ mw) {
    int idx = blockIdx.x * blockDim.x + threadIdx.x;
    if (idx < HH * BB) g_c[idx] = 0.f;
    if (idx < TOKENS / 4) {
        if (mw[idx] > 1u) g_mask_is_byte = 1;   // benign race, same value
    }
}

// Permuted bf16 weights g_W[c'][k], c' = 4p+g (orig col g*300+p); bias too.
__global__ void wbuild_k(const float* __restrict__ Wx,
                         const float* __restrict__ Wh,
                         const float* __restrict__ bias) {
    int idx = blockIdx.x * blockDim.x + threadIdx.x;
    if (idx < NZP * KP) {
        int cp = idx / KP, k = idx % KP;
        float v = 0.f;
        if (cp < NZ && k < KTOT) {
            int p = cp >> 2, g = cp & 3;
            v = (k < EE) ? Wx[k * NZ + g * HH + p] : Wh[(k - EE) * NZ + g * HH + p];
        }
        g_W[idx] = __float2bfloat16(v);
    }
    if (idx < NZP) {
        float v = 0.f;
        if (idx < NZ) v = bias[(idx & 3) * HH + (idx >> 2)];
        g_biasP[idx] = v;
    }
}

// Gather embeddings as bf16 pairs into A images; 2 threads per token.
__global__ void gather_k(const int* __restrict__ tokens,
                         const float* __restrict__ emb) {
    int idx = blockIdx.x * blockDim.x + threadIdx.x;
    if (idx >= 2 * TOKENS) return;
    int tok_i = idx >> 1;
    int half = idx & 1;
    int b = tok_i / TT, t = tok_i - b * TT;
    const float* er = emb + (size_t)tokens[tok_i] * EE;
    uint32_t* dst = reinterpret_cast<uint32_t*>(
        g_A + ((size_t)t * BB + b) * KP);
    int q0 = half * 13;
    int q1 = half ? 25 : 13;
    for (int q = q0; q < q1; ++q) {
        __nv_bfloat162 p2 = __floats2bfloat162_rn(er[2 * q], er[2 * q + 1]);
        dst[q] = *reinterpret_cast<uint32_t*>(&p2);
    }
}

// --------- fused per-step kernel: bf16 mma.sync GEMM + gates + update ------
// grid (8, 17), 256 threads (8 warps). Warp w: M-tile rows w*16..+15, all
// 72 cols, 22 K-tiles of m16n8k16. Fragment loads are direct 4B LDS from
// layouts matching the PTX fragment maps (no ldmatrix needed).
__global__ __launch_bounds__(256) void lstm_step_k(int t) {
    extern __shared__ __align__(16) char dyn[];
    __shared__ float bias_s[GN];

    char* const As = dyn;                       // [128][720B]
    char* const Ws = dyn + AS_BYTES;            // [72][720B]
    const uint32_t sA = (uint32_t)__cvta_generic_to_shared(As);
    const uint32_t sW = (uint32_t)__cvta_generic_to_shared(Ws);

    const int tid = threadIdx.x;
    const int warp = tid >> 5;
    const int lane = tid & 31;
    const int g = lane >> 2;         // groupID
    const int tig = lane & 3;        // thread-in-group
    const int rb = blockIdx.x;
    const int cbk = blockIdx.y;
    const int pblk = cbk * POSB;

    const char* gAb = reinterpret_cast<const char*>(
        g_A + ((size_t)t * BB + rb * GM) * KP);
    const char* gWb = reinterpret_cast<const char*>(g_W + (size_t)cbk * GN * KP);

    // two K-halves, each 22 x 16B chunks per row
    auto load_half = [&](int h) {
        const int hb = h * HALF_B;
        for (int i = tid; i < ACH_H; i += 256) {
            int r = i / 22, c = i - r * 22;
            cp16(sA + r * AS_STRIDE + hb + c * 16, gAb + r * (KP * 2) + hb + c * 16);
        }
        for (int i = tid; i < WCH_H; i += 256) {
            int r = i / 22, c = i - r * 22;
            cp16(sW + r * AS_STRIDE + hb + c * 16, gWb + r * (KP * 2) + hb + c * 16);
        }
    };
    load_half(0);
    cp_commit();
    load_half(1);
    cp_commit();
    if (tid < GN) bias_s[tid] = g_biasP[cbk * GN + tid];

    float acc[NT][4];
#pragma unroll
    for (int j = 0; j < NT; ++j)
#pragma unroll
        for (int e = 0; e < 4; ++e) acc[j][e] = 0.f;

    const int m0 = warp * 16;
    const char* aRow0 = As + (m0 + g) * AS_STRIDE + tig * 4;
    const char* aRow1 = As + (m0 + g + 8) * AS_STRIDE + tig * 4;
    const char* wCol = Ws + g * AS_STRIDE + tig * 4;

    cp_wait<1>();
    __syncthreads();

#pragma unroll
    for (int half = 0; half < 2; ++half) {
        if (half == 1) {
            cp_wait<0>();
            __syncthreads();
        }
#pragma unroll
        for (int kk = 0; kk < 11; ++kk) {
            const int koff = (half * 11 + kk) * 32;      // k0*2 bytes
            uint32_t a0 = *reinterpret_cast<const uint32_t*>(aRow0 + koff);
            uint32_t a1 = *reinterpret_cast<const uint32_t*>(aRow1 + koff);
            uint32_t a2 = *reinterpret_cast<const uint32_t*>(aRow0 + koff + 16);
            uint32_t a3 = *reinterpret_cast<const uint32_t*>(aRow1 + koff + 16);
#pragma unroll
            for (int j = 0; j < NT; ++j) {
                uint32_t b0 = *reinterpret_cast<const uint32_t*>(
                    wCol + j * 8 * AS_STRIDE + koff);
                uint32_t b1 = *reinterpret_cast<const uint32_t*>(
                    wCol + j * 8 * AS_STRIDE + koff + 16);
                mma16816(acc[j][0], acc[j][1], acc[j][2], acc[j][3],
                         a0, a1, a2, a3, b0, b1);
            }
        }
    }

    // ---- epilogue (warp-local): regroup gates via shfl, LSTM update ----
    const int rowlo = rb * GM + m0 + g;
    __nv_bfloat16* gAn = g_A + ((size_t)(t + 1) * BB) * KP;

#pragma unroll
    for (int j = 0; j < NT; ++j) {
        float d0 = acc[j][0], d1 = acc[j][1], d2 = acc[j][2], d3 = acc[j][3];
        float x0 = __shfl_xor_sync(0xffffffffu, d0, 1);
        float x1 = __shfl_xor_sync(0xffffffffu, d1, 1);
        float x2 = __shfl_xor_sync(0xffffffffu, d2, 1);
        float x3 = __shfl_xor_sync(0xffffffffu, d3, 1);
        const bool odd = (tig & 1);
        float iv = odd ? x2 : d0;
        float jv = odd ? x3 : d1;
        float fv = odd ? d2 : x0;
        float ov = odd ? d3 : x1;
        int pl = 2 * j + (tig >> 1);             // local position 0..17
        int p = pblk + pl;
        int b = rowlo + (odd ? 8 : 0);
        iv += bias_s[4 * pl + 0];
        jv += bias_s[4 * pl + 1];
        fv += bias_s[4 * pl + 2];
        ov += bias_s[4 * pl + 3];
        float cn, hn = 0.f;
        if (p < HH) {
            int sidx = p * BB + b;
            float c = g_c[sidx];
            lstm_point(iv, jv, fv, ov, c, cn, hn);
            g_c[sidx] = cn;
        }
        // pack (p even, p+1) h pair -> next step's A image (k = 50+p)
        float hp = __shfl_xor_sync(0xffffffffu, hn, 2);
        if (!(tig & 2) && p < HH) {
            __nv_bfloat162 hb = __floats2bfloat162_rn(hn, hp);
            *reinterpret_cast<uint32_t*>(&gAn[(size_t)b * KP + EE + p])
                = *reinterpret_cast<uint32_t*>(&hb);
        }
    }
}

// ----------------- CE: projection + log-softmax + masked sum ----------------
// h for step t read as bf16 from A image t+1 (k = 50..349), contiguous/token.
__global__ void ce_k(const float* __restrict__ U, const float* __restrict__ b2,
                     const int* __restrict__ labels,
                     const void* __restrict__ maskp)
{
    __shared__ float Us[HH * CC];
    __shared__ float b2s[CC];
    __shared__ double sd[CE_TB];
    __shared__ int    sc[CE_TB];

    const int tid = threadIdx.x;
    const int t = blockIdx.x >> 3;
    const int b = ((blockIdx.x & 7) << 7) + tid;

    for (int i = tid; i < HH * CC; i += CE_TB) Us[i] = U[i];
    if (tid < CC) b2s[tid] = b2[tid];
    __syncthreads();

    float s0 = b2s[0], s1 = b2s[1], s2 = b2s[2], s3 = b2s[3], s4 = b2s[4];
    const uint32_t* hp = reinterpret_cast<const uint32_t*>(
        g_A + ((size_t)(t + 1) * BB + b) * KP + EE);
#pragma unroll 2
    for (int q = 0; q < HH / 2; ++q) {
        __nv_bfloat162 h2 = *reinterpret_cast<const __nv_bfloat162*>(&hp[q]);
        float h0 = __bfloat162float(h2.x);
        float h1 = __bfloat162float(h2.y);
        const float* u0 = &Us[(2 * q) * CC];
        const float* u1 = &Us[(2 * q + 1) * CC];
        s0 += h0 * u0[0] + h1 * u1[0];
        s1 += h0 * u0[1] + h1 * u1[1];
        s2 += h0 * u0[2] + h1 * u1[2];
        s3 += h0 * u0[3] + h1 * u1[3];
        s4 += h0 * u0[4] + h1 * u1[4];
    }

    float m = fmaxf(fmaxf(fmaxf(s0, s1), fmaxf(s2, s3)), s4);
    float sum = __expf(s0 - m) + __expf(s1 - m) + __expf(s2 - m)
              + __expf(s3 - m) + __expf(s4 - m);
    float lse = m + __logf(sum);
    int lab = labels[b * TT + t];
    float lc = (lab == 0) ? s0 : (lab == 1) ? s1 : (lab == 2) ? s2
             : (lab == 3) ? s3 : s4;
    float ce = lse - lc;
    int mk;
    if (g_mask_is_byte) mk = (((const unsigned char*)maskp)[b * TT + t] != 0);
    else                mk = (((const int*)maskp)[b * TT + t] != 0);

    sd[tid] = mk ? (double)ce : 0.0;
    sc[tid] = mk;
    __syncthreads();
    for (int off = CE_TB / 2; off; off >>= 1) {
        if (tid < off) { sd[tid] += sd[tid + off]; sc[tid] += sc[tid + off]; }
        __syncthreads();
    }
    if (tid == 0) { g_bsum[blockIdx.x] = sd[0]; g_bcnt[blockIdx.x] = sc[0]; }
}

__global__ void fin_k(float* out) {
    __shared__ double sd[256];
    __shared__ int    sc[256];
    int i = threadIdx.x;
    double s = 0.0; int c = 0;
    for (int j = i; j < CE_BLOCKS; j += 256) { s += g_bsum[j]; c += g_bcnt[j]; }
    sd[i] = s; sc[i] = c;
    __syncthreads();
    for (int off = 128; off; off >>= 1) {
        if (i < off) { sd[i] += sd[i + off]; sc[i] += sc[i + off]; }
        __syncthreads();
    }
    if (i == 0) out[0] = (float)(sd[0] / (double)sc[0]);
}

// ----------------- launcher -----------------
extern "C" void kernel_launch(void* const* d_in, const int* in_sizes, int n_in,
                              void* d_out, int out_size)
{
    const int*   tokens = (const int*)d_in[0];
    const int*   labels = (const int*)d_in[1];
    const void*  mask   = d_in[2];
    const float* emb    = (const float*)d_in[3];
    const float* Wx     = (const float*)d_in[4];
    const float* Wh     = (const float*)d_in[5];
    const float* bias   = (const float*)d_in[6];
    const float* U      = (const float*)d_in[7];
    const float* b2     = (const float*)d_in[8];
    float* out = (float*)d_out;

    static int smem_set = 0;
    if (!smem_set) {
        cudaFuncSetAttribute(lstm_step_k,
                             cudaFuncAttributeMaxDynamicSharedMemorySize,
                             DYN_BYTES);
        smem_set = 1;
    }

    initdetect_k<<<(HH * BB + 255) / 256, 256>>>((const unsigned int*)mask);
    wbuild_k<<<(NZP * KP + 255) / 256, 256>>>(Wx, Wh, bias);
    gather_k<<<(2 * TOKENS + 255) / 256, 256>>>(tokens, emb);

    dim3 ggrid(BB / GM, NZP / GN);                 // (8, 17) = 136 blocks
    for (int t = 0; t < TT; ++t) {
        lstm_step_k<<<ggrid, 256, DYN_BYTES>>>(t); // t=0 is launch #3 (profiled)
    }

    ce_k<<<CE_BLOCKS, CE_TB>>>(U, b2, labels, mask);
    fin_k<<<1, 256>>>(out);
    (void)in_sizes; (void)n_in; (void)out_size;
}

// round 13
// speedup vs baseline: 6.7479x; 1.0664x over previous
#include <cuda_runtime.h>
#include <cuda_bf16.h>
#include <cstdint>
#include <math.h>

// Problem constants
constexpr int BB = 1024;
constexpr int TT = 120;
constexpr int EE = 50;
constexpr int HH = 300;
constexpr int CC = 5;
constexpr int KTOT = EE + HH;        // 350
constexpr int KP = 352;              // K padded (22 * 16), cols 350/351 zero
constexpr int NZ = 4 * HH;           // 1200
constexpr int NZP = 1224;            // 17 * 72 permuted cols

// Tiling: grid (8, 17) = 136 blocks (one wave, 1 block/SM), 256 threads.
constexpr int GM = 128;
constexpr int GN = 72;               // 18 positions * 4 gates
constexpr int POSB = 18;
constexpr int NT = GN / 8;           // 9 n-tiles
constexpr int NBLK = 136;

// smem: A[128][720B] + W[72][720B] (720B row stride, conflict-free)
constexpr int AS_STRIDE = 720;
constexpr int AS_BYTES = GM * AS_STRIDE;       // 92160
constexpr int WS_BYTES = GN * AS_STRIDE;       // 51840
constexpr int DYN_BYTES = AS_BYTES + WS_BYTES; // 144000
constexpr int ACH = GM * 44;         // A 16B chunks (704B per row)
constexpr int WCH = GN * 44;

// CE kernel
constexpr int TOKENS = BB * TT;
constexpr int CE_TB = 128;
constexpr int CE_BLOCKS = TOKENS / CE_TB;      // 960

// ----------------- device scratch (no cudaMalloc allowed) -----------------
// Zero-initialized at module load; every region ever read is rewritten
// identically each replay, or never written and must be zero (pad cols,
// image-0 h region == h0 = 0).
__device__ __align__(16) __nv_bfloat16 g_A[(TT + 1) * BB * KP]; // 87.2 MB
__device__ __align__(16) __nv_bfloat16 g_W[NZP * KP];           // 0.86 MB
__device__ float    g_biasP[NZP];
__device__ double   g_bsum[CE_BLOCKS];
__device__ int      g_bcnt[CE_BLOCKS];
__device__ int      g_mask_is_byte;
__device__ unsigned g_bar_cnt;       // returns to 0 after every barrier
__device__ unsigned g_bar_phase;     // monotonic across barriers/replays

// ----------------- scalar helpers -----------------
__device__ __forceinline__ float rcp_fast(float x) {
    float y;
    asm("rcp.approx.f32 %0, %1;" : "=f"(y) : "f"(x));
    return y;
}

// exp(x) with zero MUFU: FMA-only range reduction + 2^f poly + exponent add.
__device__ __forceinline__ float exp_fma(float x) {
    float x2 = x * 1.4426950408889634f;
    x2 = fminf(fmaxf(x2, -30.0f), 30.0f);
    float biased = x2 + 12582912.0f;            // 1.5 * 2^23
    int   ni = __float_as_int(biased) - 0x4B400000;
    float n = biased - 12582912.0f;
    float f = x2 - n;
    float p = 1.5403530e-4f;
    p = fmaf(p, f, 1.3333558e-3f);
    p = fmaf(p, f, 9.6181291e-3f);
    p = fmaf(p, f, 5.5504109e-2f);
    p = fmaf(p, f, 2.4022651e-1f);
    p = fmaf(p, f, 6.9314718e-1f);
    p = fmaf(p, f, 1.0f);
    return __int_as_float(__float_as_int(p) + (ni << 23));
}

// LSTM pointwise update (validated: FMA-exp + 2 RCP).
__device__ __forceinline__ void lstm_point(float iv, float jv, float fv, float ov,
                                           float c, float& cn, float& hn) {
    float ef = exp_fma(-(fv + 1.0f));
    float ei = exp_fma(-iv);
    float ej = exp_fma(2.0f * jv);
    float eo = exp_fma(-ov);
    float Af = 1.0f + ef;
    float Ai = 1.0f + ei;
    float Aj = ej + 1.0f;
    float Nj = ej - 1.0f;
    float AiAj = Ai * Aj;
    float num = fmaf(c, AiAj, Nj * Af);
    cn = num * rcp_fast(Af * AiAj);
    float ec = exp_fma(2.0f * cn);
    hn = (ec - 1.0f) * rcp_fast((1.0f + eo) * (ec + 1.0f));
}

// ----------------- async copy helpers -----------------
__device__ __forceinline__ void cp16(uint32_t dst_smem, const void* src) {
    asm volatile("cp.async.cg.shared.global [%0], [%1], 16;"
                 :: "r"(dst_smem), "l"(src));
}
__device__ __forceinline__ void cp_commit() {
    asm volatile("cp.async.commit_group;");
}
template <int N>
__device__ __forceinline__ void cp_wait() {
    asm volatile("cp.async.wait_group %0;" :: "n"(N));
}

// mma.sync m16n8k16 bf16 (sm_80+ PTX, legal on plain sm_100 target)
__device__ __forceinline__ void mma16816(float& d0, float& d1, float& d2, float& d3,
                                         uint32_t a0, uint32_t a1, uint32_t a2,
                                         uint32_t a3, uint32_t b0, uint32_t b1) {
    asm volatile(
        "mma.sync.aligned.m16n8k16.row.col.f32.bf16.bf16.f32 "
        "{%0,%1,%2,%3}, {%4,%5,%6,%7}, {%8,%9}, {%0,%1,%2,%3};"
        : "+f"(d0), "+f"(d1), "+f"(d2), "+f"(d3)
        : "r"(a0), "r"(a1), "r"(a2), "r"(a3), "r"(b0), "r"(b1));
}

// ----------------- setup kernels -----------------

__global__ void detect_k(const unsigned int* __restrict__ mw) {
    int idx = blockIdx.x * blockDim.x + threadIdx.x;
    if (idx < TOKENS / 4) {
        if (mw[idx] > 1u) g_mask_is_byte = 1;   // benign race, same value
    }
}

// Permuted bf16 weights g_W[c'][k], c' = 4p+g (orig col g*300+p); bias too.
__global__ void wbuild_k(const float* __restrict__ Wx,
                         const float* __restrict__ Wh,
                         const float* __restrict__ bias) {
    int idx = blockIdx.x * blockDim.x + threadIdx.x;
    if (idx < NZP * KP) {
        int cp = idx / KP, k = idx % KP;
        float v = 0.f;
        if (cp < NZ && k < KTOT) {
            int p = cp >> 2, g = cp & 3;
            v = (k < EE) ? Wx[k * NZ + g * HH + p] : Wh[(k - EE) * NZ + g * HH + p];
        }
        g_W[idx] = __float2bfloat16(v);
    }
    if (idx < NZP) {
        float v = 0.f;
        if (idx < NZ) v = bias[(idx & 3) * HH + (idx >> 2)];
        g_biasP[idx] = v;
    }
}

// Gather embeddings as bf16 pairs into A images; 2 threads per token.
__global__ void gather_k(const int* __restrict__ tokens,
                         const float* __restrict__ emb) {
    int idx = blockIdx.x * blockDim.x + threadIdx.x;
    if (idx >= 2 * TOKENS) return;
    int tok_i = idx >> 1;
    int half = idx & 1;
    int b = tok_i / TT, t = tok_i - b * TT;
    const float* er = emb + (size_t)tokens[tok_i] * EE;
    uint32_t* dst = reinterpret_cast<uint32_t*>(
        g_A + ((size_t)t * BB + b) * KP);
    int q0 = half * 13;
    int q1 = half ? 25 : 13;
    for (int q = q0; q < q1; ++q) {
        __nv_bfloat162 p2 = __floats2bfloat162_rn(er[2 * q], er[2 * q + 1]);
        dst[q] = *reinterpret_cast<uint32_t*>(&p2);
    }
}

// --------- persistent kernel: all 120 LSTM steps, W resident in smem -------
// grid (8, 17) = 136 blocks <= 148 SMs at 1 block/SM: single wave, so the
// software grid barrier is safe. c lives in registers (fixed (p,b)->thread
// ownership across steps). Per step only the 88 KB A tile is re-loaded
// (cp.async.cg -> L2-coherent, so cross-SM h handoff needs no L1 flush).
__global__ __launch_bounds__(256) void lstm_persist_k() {
    extern __shared__ __align__(16) char dyn[];
    __shared__ float bias_s[GN];
    __shared__ unsigned base_phase_s;

    char* const As = dyn;                       // [128][720B]
    char* const Ws = dyn + AS_BYTES;            // [72][720B]
    const uint32_t sA = (uint32_t)__cvta_generic_to_shared(As);
    const uint32_t sW = (uint32_t)__cvta_generic_to_shared(Ws);

    const int tid = threadIdx.x;
    const int warp = tid >> 5;
    const int lane = tid & 31;
    const int g = lane >> 2;         // groupID
    const int tig = lane & 3;        // thread-in-group
    const int rb = blockIdx.x;
    const int cbk = blockIdx.y;
    const int pblk = cbk * POSB;

    // Entry phase: read BEFORE any barrier; all blocks see the same value
    // (no block can bump the phase until all 136 have arrived at barrier 1).
    if (tid == 0) base_phase_s = *(volatile unsigned*)&g_bar_phase;

    // one-time loads: W tile + bias + A tile for t=0
    {
        const char* gWb = reinterpret_cast<const char*>(g_W + (size_t)cbk * GN * KP);
        for (int i = tid; i < WCH; i += 256) {
            int r = i / 44, c = i - r * 44;
            cp16(sW + r * AS_STRIDE + c * 16, gWb + r * (KP * 2) + c * 16);
        }
        const char* gAb = reinterpret_cast<const char*>(
            g_A + ((size_t)rb * GM) * KP);
        for (int i = tid; i < ACH; i += 256) {
            int r = i / 44, c = i - r * 44;
            cp16(sA + r * AS_STRIDE + c * 16, gAb + r * (KP * 2) + c * 16);
        }
        cp_commit();
        if (tid < GN) bias_s[tid] = g_biasP[cbk * GN + tid];
        cp_wait<0>();
        __syncthreads();
    }
    const unsigned base_phase = base_phase_s;

    // fragment pointers (fixed across steps)
    const int m0 = warp * 16;
    const char* aRow0 = As + (m0 + g) * AS_STRIDE + tig * 4;
    const char* aRow1 = As + (m0 + g + 8) * AS_STRIDE + tig * 4;
    const char* wCol = Ws + g * AS_STRIDE + tig * 4;
    const int rowlo = rb * GM + m0 + g;

    // per-thread cell state (fixed ownership), zero-initialized
    float creg[NT];
#pragma unroll
    for (int j = 0; j < NT; ++j) creg[j] = 0.f;

    for (int t = 0; t < TT; ++t) {
        float acc[NT][4];
#pragma unroll
        for (int j = 0; j < NT; ++j)
#pragma unroll
            for (int e = 0; e < 4; ++e) acc[j][e] = 0.f;

#pragma unroll
        for (int kk = 0; kk < 22; ++kk) {
            const int koff = kk * 32;                    // k0*2 bytes
            uint32_t a0 = *reinterpret_cast<const uint32_t*>(aRow0 + koff);
            uint32_t a1 = *reinterpret_cast<const uint32_t*>(aRow1 + koff);
            uint32_t a2 = *reinterpret_cast<const uint32_t*>(aRow0 + koff + 16);
            uint32_t a3 = *reinterpret_cast<const uint32_t*>(aRow1 + koff + 16);
#pragma unroll
            for (int j = 0; j < NT; ++j) {
                uint32_t b0 = *reinterpret_cast<const uint32_t*>(
                    wCol + j * 8 * AS_STRIDE + koff);
                uint32_t b1 = *reinterpret_cast<const uint32_t*>(
                    wCol + j * 8 * AS_STRIDE + koff + 16);
                mma16816(acc[j][0], acc[j][1], acc[j][2], acc[j][3],
                         a0, a1, a2, a3, b0, b1);
            }
        }

        // ---- epilogue: regroup gates via shfl, LSTM update, h -> A[t+1] ----
        __nv_bfloat16* gAn = g_A + ((size_t)(t + 1) * BB) * KP;
#pragma unroll
        for (int j = 0; j < NT; ++j) {
            float d0 = acc[j][0], d1 = acc[j][1], d2 = acc[j][2], d3 = acc[j][3];
            float x0 = __shfl_xor_sync(0xffffffffu, d0, 1);
            float x1 = __shfl_xor_sync(0xffffffffu, d1, 1);
            float x2 = __shfl_xor_sync(0xffffffffu, d2, 1);
            float x3 = __shfl_xor_sync(0xffffffffu, d3, 1);
            const bool odd = (tig & 1);
            float iv = odd ? x2 : d0;
            float jv = odd ? x3 : d1;
            float fv = odd ? d2 : x0;
            float ov = odd ? d3 : x1;
            int pl = 2 * j + (tig >> 1);
            int p = pblk + pl;
            int b = rowlo + (odd ? 8 : 0);
            iv += bias_s[4 * pl + 0];
            jv += bias_s[4 * pl + 1];
            fv += bias_s[4 * pl + 2];
            ov += bias_s[4 * pl + 3];
            float hn = 0.f;
            if (p < HH) {
                float cn;
                lstm_point(iv, jv, fv, ov, creg[j], cn, hn);
                creg[j] = cn;
            }
            float hp = __shfl_xor_sync(0xffffffffu, hn, 2);
            if (!(tig & 2) && p < HH) {
                __nv_bfloat162 hb = __floats2bfloat162_rn(hn, hp);
                *reinterpret_cast<uint32_t*>(&gAn[(size_t)b * KP + EE + p])
                    = *reinterpret_cast<uint32_t*>(&hb);
            }
        }

        if (t + 1 < TT) {
            // ---- grid barrier: h(t+1) visible everywhere before A reload ----
            __threadfence();
            __syncthreads();
            if (tid == 0) {
                if (atomicAdd(&g_bar_cnt, 1u) == NBLK - 1) {
                    atomicExch(&g_bar_cnt, 0u);
                    __threadfence();
                    atomicAdd(&g_bar_phase, 1u);
                } else {
                    unsigned tgt = (unsigned)(t + 1);
                    while ((*(volatile unsigned*)&g_bar_phase) - base_phase < tgt) {}
                }
                __threadfence();
            }
            __syncthreads();

            // ---- load A tile for step t+1 ----
            const char* gAb = reinterpret_cast<const char*>(
                g_A + ((size_t)(t + 1) * BB + rb * GM) * KP);
            for (int i = tid; i < ACH; i += 256) {
                int r = i / 44, c = i - r * 44;
                cp16(sA + r * AS_STRIDE + c * 16, gAb + r * (KP * 2) + c * 16);
            }
            cp_commit();
            cp_wait<0>();
            __syncthreads();
        }
    }
}

// ----------------- CE: projection + log-softmax + masked sum ----------------
// h for step t read as bf16 from A image t+1 (k = 50..349), contiguous/token.
__global__ void ce_k(const float* __restrict__ U, const float* __restrict__ b2,
                     const int* __restrict__ labels,
                     const void* __restrict__ maskp)
{
    __shared__ float Us[HH * CC];
    __shared__ float b2s[CC];
    __shared__ double sd[CE_TB];
    __shared__ int    sc[CE_TB];

    const int tid = threadIdx.x;
    const int t = blockIdx.x >> 3;
    const int b = ((blockIdx.x & 7) << 7) + tid;

    for (int i = tid; i < HH * CC; i += CE_TB) Us[i] = U[i];
    if (tid < CC) b2s[tid] = b2[tid];
    __syncthreads();

    float s0 = b2s[0], s1 = b2s[1], s2 = b2s[2], s3 = b2s[3], s4 = b2s[4];
    const uint32_t* hp = reinterpret_cast<const uint32_t*>(
        g_A + ((size_t)(t + 1) * BB + b) * KP + EE);
#pragma unroll 2
    for (int q = 0; q < HH / 2; ++q) {
        __nv_bfloat162 h2 = *reinterpret_cast<const __nv_bfloat162*>(&hp[q]);
        float h0 = __bfloat162float(h2.x);
        float h1 = __bfloat162float(h2.y);
        const float* u0 = &Us[(2 * q) * CC];
        const float* u1 = &Us[(2 * q + 1) * CC];
        s0 += h0 * u0[0] + h1 * u1[0];
        s1 += h0 * u0[1] + h1 * u1[1];
        s2 += h0 * u0[2] + h1 * u1[2];
        s3 += h0 * u0[3] + h1 * u1[3];
        s4 += h0 * u0[4] + h1 * u1[4];
    }

    float m = fmaxf(fmaxf(fmaxf(s0, s1), fmaxf(s2, s3)), s4);
    float sum = __expf(s0 - m) + __expf(s1 - m) + __expf(s2 - m)
              + __expf(s3 - m) + __expf(s4 - m);
    float lse = m + __logf(sum);
    int lab = labels[b * TT + t];
    float lc = (lab == 0) ? s0 : (lab == 1) ? s1 : (lab == 2) ? s2
             : (lab == 3) ? s3 : s4;
    float ce = lse - lc;
    int mk;
    if (g_mask_is_byte) mk = (((const unsigned char*)maskp)[b * TT + t] != 0);
    else                mk = (((const int*)maskp)[b * TT + t] != 0);

    sd[tid] = mk ? (double)ce : 0.0;
    sc[tid] = mk;
    __syncthreads();
    for (int off = CE_TB / 2; off; off >>= 1) {
        if (tid < off) { sd[tid] += sd[tid + off]; sc[tid] += sc[tid + off]; }
        __syncthreads();
    }
    if (tid == 0) { g_bsum[blockIdx.x] = sd[0]; g_bcnt[blockIdx.x] = sc[0]; }
}

__global__ void fin_k(float* out) {
    __shared__ double sd[256];
    __shared__ int    sc[256];
    int i = threadIdx.x;
    double s = 0.0; int c = 0;
    for (int j = i; j < CE_BLOCKS; j += 256) { s += g_bsum[j]; c += g_bcnt[j]; }
    sd[i] = s; sc[i] = c;
    __syncthreads();
    for (int off = 128; off; off >>= 1) {
        if (i < off) { sd[i] += sd[i + off]; sc[i] += sc[i + off]; }
        __syncthreads();
    }
    if (i == 0) out[0] = (float)(sd[0] / (double)sc[0]);
}

// ----------------- launcher -----------------
extern "C" void kernel_launch(void* const* d_in, const int* in_sizes, int n_in,
                              void* d_out, int out_size)
{
    const int*   tokens = (const int*)d_in[0];
    const int*   labels = (const int*)d_in[1];
    const void*  mask   = d_in[2];
    const float* emb    = (const float*)d_in[3];
    const float* Wx     = (const float*)d_in[4];
    const float* Wh     = (const float*)d_in[5];
    const float* bias   = (const float*)d_in[6];
    const float* U      = (const float*)d_in[7];
    const float* b2     = (const float*)d_in[8];
    float* out = (float*)d_out;

    static int smem_set = 0;
    if (!smem_set) {
        cudaFuncSetAttribute(lstm_persist_k,
                             cudaFuncAttributeMaxDynamicSharedMemorySize,
                             DYN_BYTES);
        smem_set = 1;
    }

    detect_k<<<(TOKENS / 4 + 255) / 256, 256>>>((const unsigned int*)mask);
    wbuild_k<<<(NZP * KP + 255) / 256, 256>>>(Wx, Wh, bias);
    gather_k<<<(2 * TOKENS + 255) / 256, 256>>>(tokens, emb);

    dim3 ggrid(BB / GM, NZP / GN);                 // (8, 17) = 136 blocks
    lstm_persist_k<<<ggrid, 256, DYN_BYTES>>>();   // launch #3 (profiled)

    ce_k<<<CE_BLOCKS, CE_TB>>>(U, b2, labels, mask);
    fin_k<<<1, 256>>>(out);
    (void)in_sizes; (void)n_in; (void)out_size;
}

// round 14
// speedup vs baseline: 6.8394x; 1.0136x over previous
#include <cuda_runtime.h>
#include <cuda_bf16.h>
#include <cstdint>
#include <math.h>

// Problem constants
constexpr int BB = 1024;
constexpr int TT = 120;
constexpr int EE = 50;
constexpr int HH = 300;
constexpr int CC = 5;
constexpr int KTOT = EE + HH;        // 350
constexpr int KP = 352;              // K padded (22 * 16), cols 350/351 zero
constexpr int NZ = 4 * HH;           // 1200
constexpr int NZP = 1224;            // 17 * 72 permuted cols

// Tiling: grid (8, 17) = 136 blocks (one wave, 1 block/SM), 256 threads.
constexpr int GM = 128;
constexpr int GN = 72;               // 18 positions * 4 gates
constexpr int POSB = 18;
constexpr int NT = GN / 8;           // 9 n-tiles
constexpr int NBLK = 136;

// smem: A[128][720B] + W[72][720B] (720B row stride, conflict-free)
constexpr int AS_STRIDE = 720;
constexpr int AS_BYTES = GM * AS_STRIDE;       // 92160
constexpr int WS_BYTES = GN * AS_STRIDE;       // 51840
constexpr int DYN_BYTES = AS_BYTES + WS_BYTES; // 144000
constexpr int WCH = GN * 44;         // W 16B chunks

// CE kernel
constexpr int TOKENS = BB * TT;
constexpr int CE_TB = 128;
constexpr int CE_BLOCKS = TOKENS / CE_TB;      // 960

// ----------------- device scratch (no cudaMalloc allowed) -----------------
// Zero-initialized at module load; every region ever read is rewritten
// identically each replay, or never written and must be zero (pad cols,
// image-0 h region == h0 = 0).
__device__ __align__(16) __nv_bfloat16 g_A[(TT + 1) * BB * KP]; // 87.2 MB
__device__ __align__(16) __nv_bfloat16 g_W[NZP * KP];           // 0.86 MB
__device__ float    g_biasP[NZP];
__device__ double   g_bsum[CE_BLOCKS];
__device__ int      g_bcnt[CE_BLOCKS];
__device__ int      g_mask_is_byte;
__device__ unsigned g_bar_cnt;       // returns to 0 after every barrier
__device__ unsigned g_bar_phase;     // monotonic across barriers/replays

// ----------------- scalar helpers -----------------
__device__ __forceinline__ float rcp_fast(float x) {
    float y;
    asm("rcp.approx.f32 %0, %1;" : "=f"(y) : "f"(x));
    return y;
}

// exp(x) with zero MUFU: FMA-only range reduction + 2^f poly + exponent add.
__device__ __forceinline__ float exp_fma(float x) {
    float x2 = x * 1.4426950408889634f;
    x2 = fminf(fmaxf(x2, -30.0f), 30.0f);
    float biased = x2 + 12582912.0f;            // 1.5 * 2^23
    int   ni = __float_as_int(biased) - 0x4B400000;
    float n = biased - 12582912.0f;
    float f = x2 - n;
    float p = 1.5403530e-4f;
    p = fmaf(p, f, 1.3333558e-3f);
    p = fmaf(p, f, 9.6181291e-3f);
    p = fmaf(p, f, 5.5504109e-2f);
    p = fmaf(p, f, 2.4022651e-1f);
    p = fmaf(p, f, 6.9314718e-1f);
    p = fmaf(p, f, 1.0f);
    return __int_as_float(__float_as_int(p) + (ni << 23));
}

// LSTM pointwise update (validated: FMA-exp + 2 RCP).
__device__ __forceinline__ void lstm_point(float iv, float jv, float fv, float ov,
                                           float c, float& cn, float& hn) {
    float ef = exp_fma(-(fv + 1.0f));
    float ei = exp_fma(-iv);
    float ej = exp_fma(2.0f * jv);
    float eo = exp_fma(-ov);
    float Af = 1.0f + ef;
    float Ai = 1.0f + ei;
    float Aj = ej + 1.0f;
    float Nj = ej - 1.0f;
    float AiAj = Ai * Aj;
    float num = fmaf(c, AiAj, Nj * Af);
    cn = num * rcp_fast(Af * AiAj);
    float ec = exp_fma(2.0f * cn);
    hn = (ec - 1.0f) * rcp_fast((1.0f + eo) * (ec + 1.0f));
}

// ----------------- async copy helpers -----------------
__device__ __forceinline__ void cp16(uint32_t dst_smem, const void* src) {
    asm volatile("cp.async.cg.shared.global [%0], [%1], 16;"
                 :: "r"(dst_smem), "l"(src));
}
__device__ __forceinline__ void cp_commit() {
    asm volatile("cp.async.commit_group;");
}
template <int N>
__device__ __forceinline__ void cp_wait() {
    asm volatile("cp.async.wait_group %0;" :: "n"(N));
}

// mma.sync m16n8k16 bf16 (sm_80+ PTX, legal on plain sm_100 target)
__device__ __forceinline__ void mma16816(float& d0, float& d1, float& d2, float& d3,
                                         uint32_t a0, uint32_t a1, uint32_t a2,
                                         uint32_t a3, uint32_t b0, uint32_t b1) {
    asm volatile(
        "mma.sync.aligned.m16n8k16.row.col.f32.bf16.bf16.f32 "
        "{%0,%1,%2,%3}, {%4,%5,%6,%7}, {%8,%9}, {%0,%1,%2,%3};"
        : "+f"(d0), "+f"(d1), "+f"(d2), "+f"(d3)
        : "r"(a0), "r"(a1), "r"(a2), "r"(a3), "r"(b0), "r"(b1));
}

__device__ __forceinline__ void ldsm4(uint32_t& r0, uint32_t& r1,
                                      uint32_t& r2, uint32_t& r3, uint32_t a) {
    asm volatile("ldmatrix.sync.aligned.m8n8.x4.shared.b16 {%0,%1,%2,%3}, [%4];"
                 : "=r"(r0), "=r"(r1), "=r"(r2), "=r"(r3) : "r"(a));
}
__device__ __forceinline__ void ldsm2(uint32_t& r0, uint32_t& r1, uint32_t a) {
    asm volatile("ldmatrix.sync.aligned.m8n8.x2.shared.b16 {%0,%1}, [%2];"
                 : "=r"(r0), "=r"(r1) : "r"(a));
}

// ----------------- setup kernels -----------------

__global__ void detect_k(const unsigned int* __restrict__ mw) {
    int idx = blockIdx.x * blockDim.x + threadIdx.x;
    if (idx < TOKENS / 4) {
        if (mw[idx] > 1u) g_mask_is_byte = 1;   // benign race, same value
    }
}

// Permuted bf16 weights g_W[c'][k], c' = 4p+g (orig col g*300+p); bias too.
__global__ void wbuild_k(const float* __restrict__ Wx,
                         const float* __restrict__ Wh,
                         const float* __restrict__ bias) {
    int idx = blockIdx.x * blockDim.x + threadIdx.x;
    if (idx < NZP * KP) {
        int cp = idx / KP, k = idx % KP;
        float v = 0.f;
        if (cp < NZ && k < KTOT) {
            int p = cp >> 2, g = cp & 3;
            v = (k < EE) ? Wx[k * NZ + g * HH + p] : Wh[(k - EE) * NZ + g * HH + p];
        }
        g_W[idx] = __float2bfloat16(v);
    }
    if (idx < NZP) {
        float v = 0.f;
        if (idx < NZ) v = bias[(idx & 3) * HH + (idx >> 2)];
        g_biasP[idx] = v;
    }
}

// Gather embeddings as bf16 pairs into A images; 2 threads per token.
__global__ void gather_k(const int* __restrict__ tokens,
                         const float* __restrict__ emb) {
    int idx = blockIdx.x * blockDim.x + threadIdx.x;
    if (idx >= 2 * TOKENS) return;
    int tok_i = idx >> 1;
    int half = idx & 1;
    int b = tok_i / TT, t = tok_i - b * TT;
    const float* er = emb + (size_t)tokens[tok_i] * EE;
    uint32_t* dst = reinterpret_cast<uint32_t*>(
        g_A + ((size_t)t * BB + b) * KP);
    int q0 = half * 13;
    int q1 = half ? 25 : 13;
    for (int q = q0; q < q1; ++q) {
        __nv_bfloat162 p2 = __floats2bfloat162_rn(er[2 * q], er[2 * q + 1]);
        dst[q] = *reinterpret_cast<uint32_t*>(&p2);
    }
}

// --------- persistent kernel: all 120 LSTM steps -------------------------
// ldmatrix fragments; split-K pipelined A reload: x cols (chunks 0..5,
// k0..47) prefetched into the dead A buffer BEFORE the barrier; h cols
// (chunks 6..43, k48..351; k48/49 harmlessly re-read x) as 4 cp.async
// groups after the barrier, overlapped with 5 MMA stages via
// wait_group<4..0>. t=0 initial load issues the same 5-group pattern.
__global__ __launch_bounds__(256) void lstm_persist_k() {
    extern __shared__ __align__(16) char dyn[];
    __shared__ float bias_s[GN];
    __shared__ unsigned base_phase_s;

    char* const As = dyn;                       // [128][720B]
    char* const Ws = dyn + AS_BYTES;            // [72][720B]
    const uint32_t sA = (uint32_t)__cvta_generic_to_shared(As);
    const uint32_t sW = (uint32_t)__cvta_generic_to_shared(Ws);

    const int tid = threadIdx.x;
    const int warp = tid >> 5;
    const int lane = tid & 31;
    const int g = lane >> 2;
    const int tig = lane & 3;
    const int rb = blockIdx.x;
    const int cbk = blockIdx.y;
    const int pblk = cbk * POSB;
    const int m0 = warp * 16;

    if (tid == 0) base_phase_s = *(volatile unsigned*)&g_bar_phase;

    // A chunk-column loader: columns [c0, c1) of 16B chunks for given image.
    auto load_cols = [&](const char* gbase, int c0, int c1) {
        const int span = c1 - c0;
        for (int i = tid; i < GM * span; i += 256) {
            int r = i / span, c = c0 + i - (i / span) * span;
            cp16(sA + r * AS_STRIDE + c * 16, gbase + r * (KP * 2) + c * 16);
        }
    };

    // initial loads: group0 = W + bias + A x-cols; groups 1..4 = A h-cols
    {
        const char* gWb = reinterpret_cast<const char*>(g_W + (size_t)cbk * GN * KP);
        for (int i = tid; i < WCH; i += 256) {
            int r = i / 44, c = i - (i / 44) * 44;
            cp16(sW + r * AS_STRIDE + c * 16, gWb + r * (KP * 2) + c * 16);
        }
        const char* gAb = reinterpret_cast<const char*>(g_A + ((size_t)rb * GM) * KP);
        load_cols(gAb, 0, 6);  cp_commit();
        load_cols(gAb, 6, 16); cp_commit();
        load_cols(gAb, 16, 26); cp_commit();
        load_cols(gAb, 26, 36); cp_commit();
        load_cols(gAb, 36, 44); cp_commit();
        if (tid < GN) bias_s[tid] = g_biasP[cbk * GN + tid];
    }
    __syncthreads();
    const unsigned base_phase = base_phase_s;

    // ldmatrix lane addresses (fixed across steps; +kk*32 per k-tile)
    const int quad = lane >> 3, lr = lane & 7;
    const uint32_t aBase = sA + (uint32_t)(m0 + (quad & 1) * 8 + lr) * AS_STRIDE
                         + (uint32_t)(quad >> 1) * 16;
    uint32_t bBase[5];
#pragma unroll
    for (int jp = 0; jp < 4; ++jp)
        bBase[jp] = sW + (uint32_t)((2 * jp + (lane >> 4)) * 8 + lr) * AS_STRIDE
                  + (uint32_t)((lane >> 3) & 1) * 16;
    {
        int l2 = lane & 15;
        bBase[4] = sW + (uint32_t)(64 + (l2 & 7)) * AS_STRIDE
                 + (uint32_t)(l2 >> 3) * 16;
    }
    const int rowlo = rb * GM + m0 + g;

    float creg[NT];
#pragma unroll
    for (int j = 0; j < NT; ++j) creg[j] = 0.f;

    float acc[NT][4];

    for (int t = 0; t < TT; ++t) {
#pragma unroll
        for (int j = 0; j < NT; ++j)
#pragma unroll
            for (int e = 0; e < 4; ++e) acc[j][e] = 0.f;

        // staged MMA over k-tiles; each stage gated on its cp.async group
        auto mma_tiles = [&](int kk0, int kk1) {
            for (int kk = kk0; kk < kk1; ++kk) {
                const uint32_t ko = (uint32_t)kk * 32;
                uint32_t a0, a1, a2, a3;
                ldsm4(a0, a1, a2, a3, aBase + ko);
#pragma unroll
                for (int jp = 0; jp < 4; ++jp) {
                    uint32_t b0, b1, b2, b3;
                    ldsm4(b0, b1, b2, b3, bBase[jp] + ko);
                    mma16816(acc[2 * jp][0], acc[2 * jp][1],
                             acc[2 * jp][2], acc[2 * jp][3],
                             a0, a1, a2, a3, b0, b1);
                    mma16816(acc[2 * jp + 1][0], acc[2 * jp + 1][1],
                             acc[2 * jp + 1][2], acc[2 * jp + 1][3],
                             a0, a1, a2, a3, b2, b3);
                }
                uint32_t c0, c1;
                ldsm2(c0, c1, bBase[4] + ko);
                mma16816(acc[8][0], acc[8][1], acc[8][2], acc[8][3],
                         a0, a1, a2, a3, c0, c1);
            }
        };

        cp_wait<4>(); __syncthreads(); mma_tiles(0, 3);    // x cols
        cp_wait<3>(); __syncthreads(); mma_tiles(3, 8);    // k48..127
        cp_wait<2>(); __syncthreads(); mma_tiles(8, 13);   // k128..207
        cp_wait<1>(); __syncthreads(); mma_tiles(13, 18);  // k208..287
        cp_wait<0>(); __syncthreads(); mma_tiles(18, 22);  // k288..351
        __syncthreads();   // all warps done with As before x-prefetch

        // prefetch x cols of A(t+1) into dead As (hidden by epilogue+barrier)
        if (t + 1 < TT) {
            const char* gAb = reinterpret_cast<const char*>(
                g_A + ((size_t)(t + 1) * BB + rb * GM) * KP);
            load_cols(gAb, 0, 6);
            cp_commit();
        }

        // ---- epilogue: regroup gates via shfl, LSTM update, h -> A[t+1] ----
        __nv_bfloat16* gAn = g_A + ((size_t)(t + 1) * BB) * KP;
#pragma unroll
        for (int j = 0; j < NT; ++j) {
            float d0 = acc[j][0], d1 = acc[j][1], d2 = acc[j][2], d3 = acc[j][3];
            float x0 = __shfl_xor_sync(0xffffffffu, d0, 1);
            float x1 = __shfl_xor_sync(0xffffffffu, d1, 1);
            float x2 = __shfl_xor_sync(0xffffffffu, d2, 1);
            float x3 = __shfl_xor_sync(0xffffffffu, d3, 1);
            const bool odd = (tig & 1);
            float iv = odd ? x2 : d0;
            float jv = odd ? x3 : d1;
            float fv = odd ? d2 : x0;
            float ov = odd ? d3 : x1;
            int pl = 2 * j + (tig >> 1);
            int p = pblk + pl;
            int b = rowlo + (odd ? 8 : 0);
            iv += bias_s[4 * pl + 0];
            jv += bias_s[4 * pl + 1];
            fv += bias_s[4 * pl + 2];
            ov += bias_s[4 * pl + 3];
            float hn = 0.f;
            if (p < HH) {
                float cn;
                lstm_point(iv, jv, fv, ov, creg[j], cn, hn);
                creg[j] = cn;
            }
            float hp = __shfl_xor_sync(0xffffffffu, hn, 2);
            if (!(tig & 2) && p < HH) {
                __nv_bfloat162 hb = __floats2bfloat162_rn(hn, hp);
                *reinterpret_cast<uint32_t*>(&gAn[(size_t)b * KP + EE + p])
                    = *reinterpret_cast<uint32_t*>(&hb);
            }
        }

        if (t + 1 < TT) {
            // ---- grid barrier: h(t+1) visible everywhere before h reload ----
            __threadfence();
            __syncthreads();
            if (tid == 0) {
                if (atomicAdd(&g_bar_cnt, 1u) == NBLK - 1) {
                    atomicExch(&g_bar_cnt, 0u);
                    __threadfence();
                    atomicAdd(&g_bar_phase, 1u);
                } else {
                    unsigned tgt = (unsigned)(t + 1);
                    while ((*(volatile unsigned*)&g_bar_phase) - base_phase < tgt) {}
                }
                __threadfence();
            }
            __syncthreads();

            // ---- issue h-col loads for step t+1 (4 pipelined groups) ----
            const char* gAb = reinterpret_cast<const char*>(
                g_A + ((size_t)(t + 1) * BB + rb * GM) * KP);
            load_cols(gAb, 6, 16);  cp_commit();
            load_cols(gAb, 16, 26); cp_commit();
            load_cols(gAb, 26, 36); cp_commit();
            load_cols(gAb, 36, 44); cp_commit();
        }
    }
}

// ----------------- CE: projection + log-softmax + masked sum ----------------
// h for step t read as bf16 from A image t+1 (k = 50..349), contiguous/token.
__global__ void ce_k(const float* __restrict__ U, const float* __restrict__ b2,
                     const int* __restrict__ labels,
                     const void* __restrict__ maskp)
{
    __shared__ float Us[HH * CC];
    __shared__ float b2s[CC];
    __shared__ double sd[CE_TB];
    __shared__ int    sc[CE_TB];

    const int tid = threadIdx.x;
    const int t = blockIdx.x >> 3;
    const int b = ((blockIdx.x & 7) << 7) + tid;

    for (int i = tid; i < HH * CC; i += CE_TB) Us[i] = U[i];
    if (tid < CC) b2s[tid] = b2[tid];
    __syncthreads();

    float s0 = b2s[0], s1 = b2s[1], s2 = b2s[2], s3 = b2s[3], s4 = b2s[4];
    const uint32_t* hp = reinterpret_cast<const uint32_t*>(
        g_A + ((size_t)(t + 1) * BB + b) * KP + EE);
#pragma unroll 2
    for (int q = 0; q < HH / 2; ++q) {
        __nv_bfloat162 h2 = *reinterpret_cast<const __nv_bfloat162*>(&hp[q]);
        float h0 = __bfloat162float(h2.x);
        float h1 = __bfloat162float(h2.y);
        const float* u0 = &Us[(2 * q) * CC];
        const float* u1 = &Us[(2 * q + 1) * CC];
        s0 += h0 * u0[0] + h1 * u1[0];
        s1 += h0 * u0[1] + h1 * u1[1];
        s2 += h0 * u0[2] + h1 * u1[2];
        s3 += h0 * u0[3] + h1 * u1[3];
        s4 += h0 * u0[4] + h1 * u1[4];
    }

    float m = fmaxf(fmaxf(fmaxf(s0, s1), fmaxf(s2, s3)), s4);
    float sum = __expf(s0 - m) + __expf(s1 - m) + __expf(s2 - m)
              + __expf(s3 - m) + __expf(s4 - m);
    float lse = m + __logf(sum);
    int lab = labels[b * TT + t];
    float lc = (lab == 0) ? s0 : (lab == 1) ? s1 : (lab == 2) ? s2
             : (lab == 3) ? s3 : s4;
    float ce = lse - lc;
    int mk;
    if (g_mask_is_byte) mk = (((const unsigned char*)maskp)[b * TT + t] != 0);
    else                mk = (((const int*)maskp)[b * TT + t] != 0);

    sd[tid] = mk ? (double)ce : 0.0;
    sc[tid] = mk;
    __syncthreads();
    for (int off = CE_TB / 2; off; off >>= 1) {
        if (tid < off) { sd[tid] += sd[tid + off]; sc[tid] += sc[tid + off]; }
        __syncthreads();
    }
    if (tid == 0) { g_bsum[blockIdx.x] = sd[0]; g_bcnt[blockIdx.x] = sc[0]; }
}

__global__ void fin_k(float* out) {
    __shared__ double sd[256];
    __shared__ int    sc[256];
    int i = threadIdx.x;
    double s = 0.0; int c = 0;
    for (int j = i; j < CE_BLOCKS; j += 256) { s += g_bsum[j]; c += g_bcnt[j]; }
    sd[i] = s; sc[i] = c;
    __syncthreads();
    for (int off = 128; off; off >>= 1) {
        if (i < off) { sd[i] += sd[i + off]; sc[i] += sc[i + off]; }
        __syncthreads();
    }
    if (i == 0) out[0] = (float)(sd[0] / (double)sc[0]);
}

// ----------------- launcher -----------------
extern "C" void kernel_launch(void* const* d_in, const int* in_sizes, int n_in,
                              void* d_out, int out_size)
{
    const int*   tokens = (const int*)d_in[0];
    const int*   labels = (const int*)d_in[1];
    const void*  mask   = d_in[2];
    const float* emb    = (const float*)d_in[3];
    const float* Wx     = (const float*)d_in[4];
    const float* Wh     = (const float*)d_in[5];
    const float* bias   = (const float*)d_in[6];
    const float* U      = (const float*)d_in[7];
    const float* b2     = (const float*)d_in[8];
    float* out = (float*)d_out;

    static int smem_set = 0;
    if (!smem_set) {
        cudaFuncSetAttribute(lstm_persist_k,
                             cudaFuncAttributeMaxDynamicSharedMemorySize,
                             DYN_BYTES);
        smem_set = 1;
    }

    detect_k<<<(TOKENS / 4 + 255) / 256, 256>>>((const unsigned int*)mask);
    wbuild_k<<<(NZP * KP + 255) / 256, 256>>>(Wx, Wh, bias);
    gather_k<<<(2 * TOKENS + 255) / 256, 256>>>(tokens, emb);

    dim3 ggrid(BB / GM, NZP / GN);                 // (8, 17) = 136 blocks
    lstm_persist_k<<<ggrid, 256, DYN_BYTES>>>();   // launch #3 (profiled)

    ce_k<<<CE_BLOCKS, CE_TB>>>(U, b2, labels, mask);
    fin_k<<<1, 256>>>(out);
    (void)in_sizes; (void)n_in; (void)out_size;
}